// round 16
// baseline (speedup 1.0000x reference)
#include <cuda_runtime.h>
#include <cuda_fp16.h>
#include <cstdint>

#define N_    32
#define CIN   256
#define COUT  512
#define HW    3136
#define EPSV  1e-5f
#define DW_TH 4.0f
#define PW_TH 1e-3f

// GEMM tiling: CTA 64(hw) x 128(o), K chunks of 32, 6-stage cp.async pipe
// 512 threads: 16 warps, warp tile 16(hw) x 32(o)
#define TM_HW  64
#define TN_O   128
#define KC     32
#define NKC    (CIN / KC)          // 8
#define NST    6
// smem stage layout
#define YROW   144                 // 64 hw * 2B = 128B + 16 pad
#define WROW   80                  // 32 k  * 2B = 64B  + 16 pad
#define OFF_Y  0
#define OFF_W  (KC * YROW)                   // 4608
#define STAGE  (KC * YROW + TN_O * WROW)     // 14848
#define OFF_EPI (NST * STAGE)                // 89088
#define SMEM_PW (OFF_EPI + TN_O * 8)         // 90112 (a2s + sh2s only)

// ---------------- scratch (no allocs allowed) ----------------
__device__ __align__(16) __half g_yh[(size_t)N_ * CIN * HW];   // 51.5 MB
__device__ __align__(16) __half g_wh[COUT * CIN];
__device__ int g_zmax[N_ * COUT];

// ---------------- helpers ----------------
__device__ __forceinline__ uint32_t smem_u32(const void* p) {
    uint32_t a;
    asm("{ .reg .u64 t; cvta.to.shared.u64 t, %1; cvt.u32.u64 %0, t; }" : "=r"(a) : "l"(p));
    return a;
}
__device__ __forceinline__ void cp16(uint32_t saddr, const void* g) {
    asm volatile("cp.async.cg.shared.global [%0], [%1], 16;" :: "r"(saddr), "l"(g));
}
#define CP_COMMIT() asm volatile("cp.async.commit_group;" ::: "memory")
#define CP_WAIT4()  asm volatile("cp.async.wait_group 4;" ::: "memory")

__device__ __forceinline__ void ldsm4(uint32_t* r, uint32_t a) {
    asm volatile("ldmatrix.sync.aligned.m8n8.x4.shared.b16 {%0,%1,%2,%3}, [%4];"
                 : "=r"(r[0]), "=r"(r[1]), "=r"(r[2]), "=r"(r[3]) : "r"(a));
}
__device__ __forceinline__ void ldsm4t(uint32_t* r, uint32_t a) {
    asm volatile("ldmatrix.sync.aligned.m8n8.x4.trans.shared.b16 {%0,%1,%2,%3}, [%4];"
                 : "=r"(r[0]), "=r"(r[1]), "=r"(r[2]), "=r"(r[3]) : "r"(a));
}
__device__ __forceinline__ void mma_f16(float* c, const uint32_t* a, uint32_t b0, uint32_t b1) {
    asm volatile("mma.sync.aligned.m16n8k16.row.col.f32.f16.f16.f32 "
                 "{%0,%1,%2,%3}, {%4,%5,%6,%7}, {%8,%9}, {%0,%1,%2,%3};"
                 : "+f"(c[0]), "+f"(c[1]), "+f"(c[2]), "+f"(c[3])
                 : "r"(a[0]), "r"(a[1]), "r"(a[2]), "r"(a[3]), "r"(b0), "r"(b1));
}

// ---------------------------------------------------------------------------
// K1: depthwise 3x3 + bias + BN1 + ReLU + per-plane cut; writes fp16 (half2)
// Sliding-window column strips (register reuse down the column).
// ---------------------------------------------------------------------------
__global__ __launch_bounds__(224)
void k_dw(const float* __restrict__ x,
          const float* __restrict__ dww,  const float* __restrict__ dwb,
          const float* __restrict__ g1,   const float* __restrict__ b1,
          const float* __restrict__ m1,   const float* __restrict__ v1,
          const float* __restrict__ pw)
{
    __shared__ __align__(8) float sx[58 * 58];
    __shared__ float wmax[8];

    const int bid = blockIdx.x;            // n*CIN + c
    const int c   = bid & (CIN - 1);
    const int tid = threadIdx.x;
    const float* __restrict__ xp = x + (size_t)bid * HW;

    // folded k_prep
    if (tid < 16) {
        int i = bid * 16 + tid;
        g_wh[i] = __float2half_rn(pw[i]);
    } else if (tid < 18) {
        g_zmax[bid * 2 + (tid - 16)] = 0;
    }

    #pragma unroll
    for (int it = 0; it < 14; ++it) {
        int i = tid + it * 224;
        int r = i / 56, q = i - r * 56;
        sx[(r + 1) * 58 + q + 1] = xp[i];
    }
    if (tid < 58) {
        sx[tid] = 0.f;
        sx[57 * 58 + tid] = 0.f;
        sx[tid * 58] = 0.f;
        sx[tid * 58 + 57] = 0.f;
    }

    const float ww0 = __ldg(&dww[c*9+0]), ww1 = __ldg(&dww[c*9+1]), ww2 = __ldg(&dww[c*9+2]);
    const float ww3 = __ldg(&dww[c*9+3]), ww4 = __ldg(&dww[c*9+4]), ww5 = __ldg(&dww[c*9+5]);
    const float ww6 = __ldg(&dww[c*9+6]), ww7 = __ldg(&dww[c*9+7]), ww8 = __ldg(&dww[c*9+8]);
    const float a  = __ldg(&g1[c]) * rsqrtf(__ldg(&v1[c]) + EPSV);
    const float sh = __ldg(&b1[c]) - __ldg(&m1[c]) * a + __ldg(&dwb[c]) * a;

    __syncthreads();

    const int cp = tid % 28;
    const int rg = tid / 28;
    const int wb = cp * 2;
    const float* q = sx + (rg * 7) * 58 + wb;

    float2 r0a = *(const float2*)(q);        float2 r0b = *(const float2*)(q + 2);
    float2 r1a = *(const float2*)(q + 58);   float2 r1b = *(const float2*)(q + 60);

    float va[7], vb[7];
    float lmax = 0.f;
    #pragma unroll
    for (int j = 0; j < 7; ++j) {
        float2 r2a = *(const float2*)(q + 116);
        float2 r2b = *(const float2*)(q + 118);
        float acc0 = r0a.x*ww0 + r0a.y*ww1 + r0b.x*ww2
                   + r1a.x*ww3 + r1a.y*ww4 + r1b.x*ww5
                   + r2a.x*ww6 + r2a.y*ww7 + r2b.x*ww8;
        float acc1 = r0a.y*ww0 + r0b.x*ww1 + r0b.y*ww2
                   + r1a.y*ww3 + r1b.x*ww4 + r1b.y*ww5
                   + r2a.y*ww6 + r2b.x*ww7 + r2b.y*ww8;
        va[j] = fmaxf(fmaf(acc0, a, sh), 0.f);
        vb[j] = fmaxf(fmaf(acc1, a, sh), 0.f);
        lmax = fmaxf(lmax, fmaxf(va[j], vb[j]));
        r0a = r1a; r0b = r1b; r1a = r2a; r1b = r2b;
        q += 58;
    }
    #pragma unroll
    for (int o = 16; o; o >>= 1) lmax = fmaxf(lmax, __shfl_xor_sync(~0u, lmax, o));
    if ((tid & 31) == 0) wmax[tid >> 5] = lmax;
    __syncthreads();
    if (tid == 0) {
        float m = wmax[0];
        #pragma unroll
        for (int i = 1; i < 7; ++i) m = fmaxf(m, wmax[i]);
        wmax[0] = m;
    }
    __syncthreads();
    const bool cut = wmax[0] < DW_TH;

    __half2* __restrict__ yp = (__half2*)(g_yh + (size_t)bid * HW);
    #pragma unroll
    for (int j = 0; j < 7; ++j) {
        float f0 = cut ? 0.f : va[j], f1 = cut ? 0.f : vb[j];
        yp[(rg * 7 + j) * 28 + cp] = __floats2half2_rn(f0, f1);
    }
}

// ---------------------------------------------------------------------------
// K2: mma.sync fp16 single-pass GEMM, 512 threads (16 warps, warp tile 16x32).
// KC=32, 6-stage pipe (depth 5). Fused BN2 + ReLU; shuffle-max epilogue.
// ---------------------------------------------------------------------------
__global__ __launch_bounds__(512, 2)
void k_pw(const float* __restrict__ pb,
          const float* __restrict__ g2,  const float* __restrict__ b2v,
          const float* __restrict__ m2,  const float* __restrict__ v2,
          float* __restrict__ out)
{
    extern __shared__ char smem[];
    const uint32_t sb = smem_u32(smem);
    const int tid  = threadIdx.x;
    const int wid  = tid >> 5;
    const int lane = tid & 31;
    const int wm   = wid & 3;          // 4 m-warps (hw, 16 each)
    const int wn   = wid >> 2;         // 4 n-warps (o, 32 each)
    const int qg   = lane >> 3;
    const int rr   = lane & 7;
    const int g    = lane >> 2;
    const int t    = lane & 3;

    const int o0  = blockIdx.x * TN_O;     // 4
    const int hw0 = blockIdx.y * TM_HW;    // 49
    const int n   = blockIdx.z;            // 32

    float* a2s  = (float*)(smem + OFF_EPI);
    float* sh2s = (float*)(smem + OFF_EPI + TN_O * 4);
    if (tid < TN_O) {
        const int o = o0 + tid;
        float a2 = __ldg(&g2[o]) * rsqrtf(__ldg(&v2[o]) + EPSV);
        a2s[tid]  = a2;
        sh2s[tid] = __ldg(&b2v[o]) - __ldg(&m2[o]) * a2 + __ldg(&pb[o]) * a2;
    }

    const __half* __restrict__ yn = g_yh + (size_t)n * CIN * HW;

    auto fill = [&](int slot, int ck) {
        const uint32_t s0 = sb + slot * STAGE;
        const int k0 = ck * KC;
        if (tid < 256) {   // Y: 32 rows x 8 chunks = 256 cp
            int row = tid >> 3, ch = tid & 7;
            cp16(s0 + OFF_Y + row * YROW + ch * 16,
                 yn + (size_t)(k0 + row) * HW + hw0 + ch * 8);
        }
        {   // W: 128 rows x 4 chunks = 512 cp
            int row = tid >> 2, ch = tid & 3;
            cp16(s0 + OFF_W + row * WROW + ch * 16,
                 g_wh + (size_t)(o0 + row) * CIN + k0 + ch * 8);
        }
    };

    float acc[4][4];
    #pragma unroll
    for (int j = 0; j < 4; ++j)
        #pragma unroll
        for (int r = 0; r < 4; ++r) acc[j][r] = 0.f;

    fill(0, 0); CP_COMMIT();
    fill(1, 1); CP_COMMIT();
    fill(2, 2); CP_COMMIT();
    fill(3, 3); CP_COMMIT();
    fill(4, 4); CP_COMMIT();

    // A (Y, trans): row = s*16 + aRow ; col byte = wm*32 + (qg&1)*16
    const uint32_t aRow  = (qg >> 1) * 8 + rr;
    const uint32_t aColB = wm * 32 + (qg & 1) * 16;
    // B (W): row = wn*32 + jp*16 + (qg>>1)*8 + rr ; col byte = s*32 + (qg&1)*16
    const uint32_t bRow  = wn * 32 + (qg >> 1) * 8 + rr;
    const uint32_t bColB = (qg & 1) * 16;

    int slot = 0, fslot = 5;
    for (int ck = 0; ck < NKC; ++ck) {
        CP_WAIT4();
        __syncthreads();
        const uint32_t s0 = sb + slot * STAGE;
        const uint32_t yB = s0 + OFF_Y;
        const uint32_t wB = s0 + OFF_W;

        #pragma unroll
        for (int s = 0; s < KC / 16; ++s) {
            uint32_t bm[2][4];
            #pragma unroll
            for (int jp = 0; jp < 2; ++jp)
                ldsm4(bm[jp], wB + (bRow + jp * 16) * WROW + bColB + s * 32);
            uint32_t av[4];
            ldsm4t(av, yB + (s * 16 + aRow) * YROW + aColB);
            #pragma unroll
            for (int jp = 0; jp < 2; ++jp) {
                #pragma unroll
                for (int jj = 0; jj < 2; ++jj)
                    mma_f16(acc[jp * 2 + jj], av, bm[jp][jj * 2], bm[jp][jj * 2 + 1]);
            }
        }
        if (ck + 5 < NKC) fill(fslot, ck + 5);
        CP_COMMIT();
        if (++slot == NST) slot = 0;
        if (++fslot == NST) fslot = 0;
    }

    // ---- epilogue: BN2+ReLU+store, per-col max in registers ----
    float cmax[8];
    #pragma unroll
    for (int k = 0; k < 8; ++k) cmax[k] = 0.f;

    float* __restrict__ outn = out + (size_t)n * COUT * HW;
    const int hwa = hw0 + wm * 16 + g;
    #pragma unroll
    for (int j = 0; j < 4; ++j) {
        const int col = wn * 32 + j * 8 + t * 2;
        const int o   = o0 + col;
        const float a20 = a2s[col],     sh0 = sh2s[col];
        const float a21 = a2s[col + 1], sh1 = sh2s[col + 1];
        float z0 = fmaxf(fmaf(acc[j][0], a20, sh0), 0.f);
        float z1 = fmaxf(fmaf(acc[j][1], a21, sh1), 0.f);
        float z2 = fmaxf(fmaf(acc[j][2], a20, sh0), 0.f);
        float z3 = fmaxf(fmaf(acc[j][3], a21, sh1), 0.f);
        outn[(size_t)o * HW + hwa]           = z0;
        outn[(size_t)(o + 1) * HW + hwa]     = z1;
        outn[(size_t)o * HW + hwa + 8]       = z2;
        outn[(size_t)(o + 1) * HW + hwa + 8] = z3;
        cmax[j * 2]     = fmaxf(z0, z2);
        cmax[j * 2 + 1] = fmaxf(z1, z3);
    }
    // reduce across g lanes (lane bits 2..4)
    #pragma unroll
    for (int k = 0; k < 8; ++k) {
        #pragma unroll
        for (int off = 4; off <= 16; off <<= 1)
            cmax[k] = fmaxf(cmax[k], __shfl_xor_sync(0xffffffffu, cmax[k], off));
    }
    if (g == 0) {   // lanes 0..3 (t = lane)
        #pragma unroll
        for (int k = 0; k < 8; ++k) {
            const int col = wn * 32 + (k >> 1) * 8 + t * 2 + (k & 1);
            atomicMax(&g_zmax[n * COUT + o0 + col], __float_as_int(cmax[k]));
        }
    }
}

// ---------------------------------------------------------------------------
// K3: zero planes whose max < 1e-3
// ---------------------------------------------------------------------------
__global__ __launch_bounds__(256)
void k_cut(float* __restrict__ out)
{
    const int base = blockIdx.x * 8;
    for (int p = 0; p < 8; ++p) {
        const int plane = base + p;
        if (__int_as_float(g_zmax[plane]) >= PW_TH) continue;
        float* __restrict__ q = out + (size_t)plane * HW;
        for (int i = threadIdx.x; i < HW; i += 256) q[i] = 0.f;
    }
}

// ---------------------------------------------------------------------------
extern "C" void kernel_launch(void* const* d_in, const int* in_sizes, int n_in,
                              void* d_out, int out_size)
{
    const float* x    = (const float*)d_in[0];
    const float* dww  = (const float*)d_in[1];
    const float* dwb  = (const float*)d_in[2];
    const float* g1   = (const float*)d_in[3];
    const float* b1   = (const float*)d_in[4];
    const float* m1   = (const float*)d_in[5];
    const float* v1   = (const float*)d_in[6];
    const float* pw   = (const float*)d_in[7];
    const float* pb   = (const float*)d_in[8];
    const float* g2   = (const float*)d_in[9];
    const float* b2   = (const float*)d_in[10];
    const float* m2   = (const float*)d_in[11];
    const float* v2   = (const float*)d_in[12];
    float* out = (float*)d_out;

    cudaFuncSetAttribute(k_pw, cudaFuncAttributeMaxDynamicSharedMemorySize, SMEM_PW);

    k_dw<<<N_ * CIN, 224>>>(x, dww, dwb, g1, b1, m1, v1, pw);
    dim3 grid(COUT / TN_O, HW / TM_HW, N_);   // 4 x 49 x 32 (o fastest for Y L2 reuse)
    k_pw<<<grid, 512, SMEM_PW>>>(pb, g2, b2, m2, v2, out);
    k_cut<<<(N_ * COUT) / 8, 256>>>(out);
}

// round 17
// speedup vs baseline: 1.2892x; 1.2892x over previous
#include <cuda_runtime.h>
#include <cuda_fp16.h>
#include <cstdint>

#define N_    32
#define CIN   256
#define COUT  512
#define HW    3136
#define EPSV  1e-5f
#define DW_TH 4.0f
#define PW_TH 1e-3f

// GEMM tiling: CTA 64(hw) x 128(o), K chunks of 32, 7-stage cp.async pipe
#define TM_HW  64
#define TN_O   128
#define KC     32
#define NKC    (CIN / KC)          // 8
#define NST    7
// smem stage layout
#define YROW   144                 // 64 hw * 2B = 128B + 16 pad
#define WROW   80                  // 32 k  * 2B = 64B  + 16 pad
#define OFF_Y  0
#define OFF_W  (KC * YROW)                   // 4608
#define STAGE  (KC * YROW + TN_O * WROW)     // 14848
#define OFF_EPI (NST * STAGE)                // 103936
#define SMEM_PW (OFF_EPI + TN_O * 8)         // 104960 (a2s + sh2s only)

// ---------------- scratch (no allocs allowed) ----------------
__device__ __align__(16) __half g_yh[(size_t)N_ * CIN * HW];   // 51.5 MB
__device__ __align__(16) __half g_wh[COUT * CIN];
__device__ int g_zmax[N_ * COUT];

// ---------------- helpers ----------------
__device__ __forceinline__ uint32_t smem_u32(const void* p) {
    uint32_t a;
    asm("{ .reg .u64 t; cvta.to.shared.u64 t, %1; cvt.u32.u64 %0, t; }" : "=r"(a) : "l"(p));
    return a;
}
__device__ __forceinline__ void cp16(uint32_t saddr, const void* g) {
    asm volatile("cp.async.cg.shared.global [%0], [%1], 16;" :: "r"(saddr), "l"(g));
}
#define CP_COMMIT() asm volatile("cp.async.commit_group;" ::: "memory")
#define CP_WAIT5()  asm volatile("cp.async.wait_group 5;" ::: "memory")

__device__ __forceinline__ void ldsm4(uint32_t* r, uint32_t a) {
    asm volatile("ldmatrix.sync.aligned.m8n8.x4.shared.b16 {%0,%1,%2,%3}, [%4];"
                 : "=r"(r[0]), "=r"(r[1]), "=r"(r[2]), "=r"(r[3]) : "r"(a));
}
__device__ __forceinline__ void ldsm4t(uint32_t* r, uint32_t a) {
    asm volatile("ldmatrix.sync.aligned.m8n8.x4.trans.shared.b16 {%0,%1,%2,%3}, [%4];"
                 : "=r"(r[0]), "=r"(r[1]), "=r"(r[2]), "=r"(r[3]) : "r"(a));
}
__device__ __forceinline__ void mma_f16(float* c, const uint32_t* a, uint32_t b0, uint32_t b1) {
    asm volatile("mma.sync.aligned.m16n8k16.row.col.f32.f16.f16.f32 "
                 "{%0,%1,%2,%3}, {%4,%5,%6,%7}, {%8,%9}, {%0,%1,%2,%3};"
                 : "+f"(c[0]), "+f"(c[1]), "+f"(c[2]), "+f"(c[3])
                 : "r"(a[0]), "r"(a[1]), "r"(a[2]), "r"(a[3]), "r"(b0), "r"(b1));
}

// ---------------------------------------------------------------------------
// K1: depthwise 3x3 + bias + BN1 + ReLU + per-plane cut; writes fp16 (half2)
// Sliding-window column strips; div-free incremental halo indexing.
// ---------------------------------------------------------------------------
__global__ __launch_bounds__(224)
void k_dw(const float* __restrict__ x,
          const float* __restrict__ dww,  const float* __restrict__ dwb,
          const float* __restrict__ g1,   const float* __restrict__ b1,
          const float* __restrict__ m1,   const float* __restrict__ v1,
          const float* __restrict__ pw)
{
    __shared__ __align__(8) float sx[58 * 58];
    __shared__ float wmax[8];

    const int bid = blockIdx.x;            // n*CIN + c
    const int c   = bid & (CIN - 1);
    const int tid = threadIdx.x;
    const float* __restrict__ xp = x + (size_t)bid * HW;

    // folded k_prep
    if (tid < 16) {
        int i = bid * 16 + tid;
        g_wh[i] = __float2half_rn(pw[i]);
    } else if (tid < 18) {
        g_zmax[bid * 2 + (tid - 16)] = 0;
    }

    // interior load: 224 threads = exactly 4 rows of 56; row advances by 4/iter
    {
        const int r0 = tid / 56;           // computed once
        const int q0 = tid - r0 * 56;
        float* s = sx + (r0 + 1) * 58 + q0 + 1;
        const float* gp = xp + tid;
        #pragma unroll
        for (int it = 0; it < 14; ++it) {
            s[it * 4 * 58] = gp[it * 224];
        }
    }
    // perimeter zero
    if (tid < 58) {
        sx[tid] = 0.f;
        sx[57 * 58 + tid] = 0.f;
        sx[tid * 58] = 0.f;
        sx[tid * 58 + 57] = 0.f;
    }

    const float ww0 = __ldg(&dww[c*9+0]), ww1 = __ldg(&dww[c*9+1]), ww2 = __ldg(&dww[c*9+2]);
    const float ww3 = __ldg(&dww[c*9+3]), ww4 = __ldg(&dww[c*9+4]), ww5 = __ldg(&dww[c*9+5]);
    const float ww6 = __ldg(&dww[c*9+6]), ww7 = __ldg(&dww[c*9+7]), ww8 = __ldg(&dww[c*9+8]);
    const float a  = __ldg(&g1[c]) * rsqrtf(__ldg(&v1[c]) + EPSV);
    const float sh = __ldg(&b1[c]) - __ldg(&m1[c]) * a + __ldg(&dwb[c]) * a;

    __syncthreads();

    const int cp = tid % 28;
    const int rg = tid / 28;
    const int wb = cp * 2;
    const float* q = sx + (rg * 7) * 58 + wb;

    float2 r0a = *(const float2*)(q);        float2 r0b = *(const float2*)(q + 2);
    float2 r1a = *(const float2*)(q + 58);   float2 r1b = *(const float2*)(q + 60);

    float va[7], vb[7];
    float lmax = 0.f;
    #pragma unroll
    for (int j = 0; j < 7; ++j) {
        float2 r2a = *(const float2*)(q + 116);
        float2 r2b = *(const float2*)(q + 118);
        float acc0 = r0a.x*ww0 + r0a.y*ww1 + r0b.x*ww2
                   + r1a.x*ww3 + r1a.y*ww4 + r1b.x*ww5
                   + r2a.x*ww6 + r2a.y*ww7 + r2b.x*ww8;
        float acc1 = r0a.y*ww0 + r0b.x*ww1 + r0b.y*ww2
                   + r1a.y*ww3 + r1b.x*ww4 + r1b.y*ww5
                   + r2a.y*ww6 + r2b.x*ww7 + r2b.y*ww8;
        va[j] = fmaxf(fmaf(acc0, a, sh), 0.f);
        vb[j] = fmaxf(fmaf(acc1, a, sh), 0.f);
        lmax = fmaxf(lmax, fmaxf(va[j], vb[j]));
        r0a = r1a; r0b = r1b; r1a = r2a; r1b = r2b;
        q += 58;
    }
    #pragma unroll
    for (int o = 16; o; o >>= 1) lmax = fmaxf(lmax, __shfl_xor_sync(~0u, lmax, o));
    if ((tid & 31) == 0) wmax[tid >> 5] = lmax;
    __syncthreads();
    if (tid == 0) {
        float m = wmax[0];
        #pragma unroll
        for (int i = 1; i < 7; ++i) m = fmaxf(m, wmax[i]);
        wmax[0] = m;
    }
    __syncthreads();
    const bool cut = wmax[0] < DW_TH;

    __half2* __restrict__ yp = (__half2*)(g_yh + (size_t)bid * HW);
    #pragma unroll
    for (int j = 0; j < 7; ++j) {
        float f0 = cut ? 0.f : va[j], f1 = cut ? 0.f : vb[j];
        yp[(rg * 7 + j) * 28 + cp] = __floats2half2_rn(f0, f1);
    }
}

// ---------------------------------------------------------------------------
// K2: mma.sync fp16 single-pass GEMM: D = Y.W ; KC=32, 7-stage pipe (depth 6).
// R14 mainloop shape (proven best). Fused BN2 + ReLU; shuffle-max epilogue.
// ---------------------------------------------------------------------------
__global__ __launch_bounds__(256, 2)
void k_pw(const float* __restrict__ pb,
          const float* __restrict__ g2,  const float* __restrict__ b2v,
          const float* __restrict__ m2,  const float* __restrict__ v2,
          float* __restrict__ out)
{
    extern __shared__ char smem[];
    const uint32_t sb = smem_u32(smem);
    const int tid  = threadIdx.x;
    const int wid  = tid >> 5;
    const int lane = tid & 31;
    const int wm   = wid & 1;          // 2 m-warps (hw, 32 each)
    const int wn   = wid >> 1;         // 4 n-warps (o, 32 each)
    const int qg   = lane >> 3;
    const int rr   = lane & 7;
    const int g    = lane >> 2;
    const int t    = lane & 3;

    const int o0  = blockIdx.x * TN_O;     // 4
    const int hw0 = blockIdx.y * TM_HW;    // 49
    const int n   = blockIdx.z;            // 32

    float* a2s  = (float*)(smem + OFF_EPI);
    float* sh2s = (float*)(smem + OFF_EPI + TN_O * 4);
    if (tid < TN_O) {
        const int o = o0 + tid;
        float a2 = __ldg(&g2[o]) * rsqrtf(__ldg(&v2[o]) + EPSV);
        a2s[tid]  = a2;
        sh2s[tid] = __ldg(&b2v[o]) - __ldg(&m2[o]) * a2 + __ldg(&pb[o]) * a2;
    }

    const __half* __restrict__ yn = g_yh + (size_t)n * CIN * HW;

    auto fill = [&](int slot, int ck) {
        const uint32_t s0 = sb + slot * STAGE;
        const int k0 = ck * KC;
        {   // Y: 32 rows x 8 chunks = 256 cp
            int row = tid >> 3, ch = tid & 7;
            cp16(s0 + OFF_Y + row * YROW + ch * 16,
                 yn + (size_t)(k0 + row) * HW + hw0 + ch * 8);
        }
        #pragma unroll
        for (int it = 0; it < 2; ++it) {   // W: 128 rows x 4 chunks = 512 cp
            int idx = tid + it * 256;
            int row = idx >> 2, ch = idx & 3;
            cp16(s0 + OFF_W + row * WROW + ch * 16,
                 g_wh + (size_t)(o0 + row) * CIN + k0 + ch * 8);
        }
    };

    float acc[2][4][4];
    #pragma unroll
    for (int i = 0; i < 2; ++i)
        #pragma unroll
        for (int j = 0; j < 4; ++j)
            #pragma unroll
            for (int r = 0; r < 4; ++r) acc[i][j][r] = 0.f;

    fill(0, 0); CP_COMMIT();
    fill(1, 1); CP_COMMIT();
    fill(2, 2); CP_COMMIT();
    fill(3, 3); CP_COMMIT();
    fill(4, 4); CP_COMMIT();
    fill(5, 5); CP_COMMIT();

    // A (Y, trans): row = s*16 + aRow ; col byte = wm*64 + (qg&1)*16 + i*32
    const uint32_t aRow  = (qg >> 1) * 8 + rr;
    const uint32_t aColB = wm * 64 + (qg & 1) * 16;
    // B (W): row = wn*32 + jp*16 + (qg>>1)*8 + rr ; col byte = s*32 + (qg&1)*16
    const uint32_t bRow  = wn * 32 + (qg >> 1) * 8 + rr;
    const uint32_t bColB = (qg & 1) * 16;

    int slot = 0, fslot = 6;
    for (int ck = 0; ck < NKC; ++ck) {
        CP_WAIT5();
        __syncthreads();
        const uint32_t s0 = sb + slot * STAGE;
        const uint32_t yB = s0 + OFF_Y;
        const uint32_t wB = s0 + OFF_W;

        #pragma unroll
        for (int s = 0; s < KC / 16; ++s) {
            uint32_t bm[2][4];
            #pragma unroll
            for (int jp = 0; jp < 2; ++jp)
                ldsm4(bm[jp], wB + (bRow + jp * 16) * WROW + bColB + s * 32);
            #pragma unroll
            for (int i = 0; i < 2; ++i) {
                uint32_t av[4];
                ldsm4t(av, yB + (s * 16 + aRow) * YROW + aColB + i * 32);
                #pragma unroll
                for (int jp = 0; jp < 2; ++jp) {
                    #pragma unroll
                    for (int jj = 0; jj < 2; ++jj)
                        mma_f16(acc[i][jp * 2 + jj], av, bm[jp][jj * 2], bm[jp][jj * 2 + 1]);
                }
            }
        }
        if (ck + 6 < NKC) fill(fslot, ck + 6);
        CP_COMMIT();
        if (++slot == NST) slot = 0;
        if (++fslot == NST) fslot = 0;
    }

    // ---- epilogue: BN2+ReLU+store, per-col max in registers ----
    float cmax[8];
    #pragma unroll
    for (int k = 0; k < 8; ++k) cmax[k] = 0.f;

    float* __restrict__ outn = out + (size_t)n * COUT * HW;
    #pragma unroll
    for (int i = 0; i < 2; ++i) {
        const int hwa = hw0 + wm * 32 + i * 16 + g;
        #pragma unroll
        for (int j = 0; j < 4; ++j) {
            const int col = wn * 32 + j * 8 + t * 2;
            const int o   = o0 + col;
            const float a20 = a2s[col],     sh0 = sh2s[col];
            const float a21 = a2s[col + 1], sh1 = sh2s[col + 1];
            float z0 = fmaxf(fmaf(acc[i][j][0], a20, sh0), 0.f);
            float z1 = fmaxf(fmaf(acc[i][j][1], a21, sh1), 0.f);
            float z2 = fmaxf(fmaf(acc[i][j][2], a20, sh0), 0.f);
            float z3 = fmaxf(fmaf(acc[i][j][3], a21, sh1), 0.f);
            outn[(size_t)o * HW + hwa]           = z0;
            outn[(size_t)(o + 1) * HW + hwa]     = z1;
            outn[(size_t)o * HW + hwa + 8]       = z2;
            outn[(size_t)(o + 1) * HW + hwa + 8] = z3;
            cmax[j * 2]     = fmaxf(cmax[j * 2],     fmaxf(z0, z2));
            cmax[j * 2 + 1] = fmaxf(cmax[j * 2 + 1], fmaxf(z1, z3));
        }
    }
    // reduce across g lanes (lane bits 2..4)
    #pragma unroll
    for (int k = 0; k < 8; ++k) {
        #pragma unroll
        for (int off = 4; off <= 16; off <<= 1)
            cmax[k] = fmaxf(cmax[k], __shfl_xor_sync(0xffffffffu, cmax[k], off));
    }
    if (g == 0) {   // lanes 0..3 (t = lane)
        #pragma unroll
        for (int k = 0; k < 8; ++k) {
            const int col = wn * 32 + (k >> 1) * 8 + t * 2 + (k & 1);
            atomicMax(&g_zmax[n * COUT + o0 + col], __float_as_int(cmax[k]));
        }
    }
}

// ---------------------------------------------------------------------------
// K3: zero planes whose max < 1e-3
// ---------------------------------------------------------------------------
__global__ __launch_bounds__(256)
void k_cut(float* __restrict__ out)
{
    const int base = blockIdx.x * 8;
    for (int p = 0; p < 8; ++p) {
        const int plane = base + p;
        if (__int_as_float(g_zmax[plane]) >= PW_TH) continue;
        float* __restrict__ q = out + (size_t)plane * HW;
        for (int i = threadIdx.x; i < HW; i += 256) q[i] = 0.f;
    }
}

// ---------------------------------------------------------------------------
extern "C" void kernel_launch(void* const* d_in, const int* in_sizes, int n_in,
                              void* d_out, int out_size)
{
    const float* x    = (const float*)d_in[0];
    const float* dww  = (const float*)d_in[1];
    const float* dwb  = (const float*)d_in[2];
    const float* g1   = (const float*)d_in[3];
    const float* b1   = (const float*)d_in[4];
    const float* m1   = (const float*)d_in[5];
    const float* v1   = (const float*)d_in[6];
    const float* pw   = (const float*)d_in[7];
    const float* pb   = (const float*)d_in[8];
    const float* g2   = (const float*)d_in[9];
    const float* b2   = (const float*)d_in[10];
    const float* m2   = (const float*)d_in[11];
    const float* v2   = (const float*)d_in[12];
    float* out = (float*)d_out;

    cudaFuncSetAttribute(k_pw, cudaFuncAttributeMaxDynamicSharedMemorySize, SMEM_PW);

    k_dw<<<N_ * CIN, 224>>>(x, dww, dwb, g1, b1, m1, v1, pw);
    dim3 grid(COUT / TN_O, HW / TM_HW, N_);   // 4 x 49 x 32 (o fastest for Y L2 reuse)
    k_pw<<<grid, 256, SMEM_PW>>>(pb, g2, b2, m2, v2, out);
    k_cut<<<(N_ * COUT) / 8, 256>>>(out);
}